// round 1
// baseline (speedup 1.0000x reference)
#include <cuda_runtime.h>

#define BB 64
#define CC 64
#define DT6 (0.1f/6.0f)

// ---------------- scratch (device globals; no allocation allowed) ----------
static __device__ float g_h1[BB*CC*128*128];  // 268MB
static __device__ float g_h2[BB*CC*64*64];    // 67MB
static __device__ float g_z [BB*CC*32*32];
static __device__ float g_g [BB*CC*32*32];
static __device__ float g_u [BB*CC*32*32];
static __device__ float g_kb[BB*CC*32*32];
static __device__ float g_ka[BB*CC*32*32];
static __device__ float g_pool[BB*CC];

// ---------------- conv1: 1->64, 3x3 VALID, 130x130 -> 128x128 --------------
__global__ __launch_bounds__(256)
void conv1_k(const float* __restrict__ x, const float* __restrict__ w,
             const float* __restrict__ bias) {
    int oc = blockIdx.y, b = blockIdx.z;
    int pix = blockIdx.x * 256 + threadIdx.x;
    int oy = pix >> 7, ox = pix & 127;
    const float* xp = x + (b * 130 + oy) * 130 + ox;
    const float* wp = w + oc * 9;
    float acc = bias[oc];
#pragma unroll
    for (int ky = 0; ky < 3; ky++)
#pragma unroll
        for (int kx = 0; kx < 3; kx++)
            acc += xp[ky * 130 + kx] * __ldg(wp + ky * 3 + kx);
    g_h1[((b * CC + oc) * 128 + oy) * 128 + ox] = acc;
}

// ---------------- GroupNorm(C,C) + ReLU, input = in + alpha*kin ------------
template <int N>
__global__ __launch_bounds__(256)
void gn_relu_k(const float* __restrict__ in, const float* __restrict__ kin,
               float alpha, const float* __restrict__ gw,
               const float* __restrict__ gb, float* __restrict__ out) {
    int bc = blockIdx.x;
    int c = bc & (CC - 1);
    int off = bc * N;
    const float* ip = in + off;
    const float* kp = kin + off;
    float s = 0.f, ss = 0.f;
    for (int i = threadIdx.x; i < N; i += 256) {
        float v = ip[i] + alpha * kp[i];
        s += v; ss += v * v;
    }
#pragma unroll
    for (int o = 16; o > 0; o >>= 1) {
        s  += __shfl_xor_sync(~0u, s, o);
        ss += __shfl_xor_sync(~0u, ss, o);
    }
    __shared__ float rs[8], rss[8];
    __shared__ float sh_sc, sh_sf;
    int wid = threadIdx.x >> 5, lid = threadIdx.x & 31;
    if (lid == 0) { rs[wid] = s; rss[wid] = ss; }
    __syncthreads();
    if (threadIdx.x == 0) {
        float S = 0.f, SS = 0.f;
#pragma unroll
        for (int i = 0; i < 8; i++) { S += rs[i]; SS += rss[i]; }
        float m = S / (float)N;
        float var = SS / (float)N - m * m;
        float sc = gw[c] * rsqrtf(var + 1e-5f);
        sh_sc = sc;
        sh_sf = gb[c] - m * sc;
    }
    __syncthreads();
    float sc = sh_sc, sf = sh_sf;
    for (int i = threadIdx.x; i < N; i += 256) {
        float v = ip[i] + alpha * kp[i];
        out[off + i] = fmaxf(v * sc + sf, 0.f);
    }
}

// ---------------- conv 4x4 stride2 pad1 (64->64 ch) ------------------------
template <int IH, int IW, int OH, int OW, int TH>
__global__ __launch_bounds__(256)
void conv4_k(const float* __restrict__ in, const float* __restrict__ w,
             const float* __restrict__ bias, float* __restrict__ out) {
    constexpr int SR = 2 * TH + 2, SC = IW + 2;
    constexpr int PPT = TH * OW / 256;
    __shared__ float sIn[SR * SC];
    __shared__ float sW[128];
    int tile = blockIdx.x, ocg = blockIdx.y, b = blockIdx.z;
    int ty0 = tile * TH;
    int tid = threadIdx.x;

    int lr[PPT], lc[PPT];
    float acc[8][PPT];
#pragma unroll
    for (int p = 0; p < PPT; p++) {
        int px = tid + 256 * p;
        lr[p] = px / OW;
        lc[p] = px % OW;
    }
#pragma unroll
    for (int oc = 0; oc < 8; oc++) {
        float bv = bias[ocg * 8 + oc];
#pragma unroll
        for (int p = 0; p < PPT; p++) acc[oc][p] = bv;
    }
    const float* inb = in + (b * CC) * IH * IW;
    int r0 = 2 * ty0 - 1;
    for (int ic = 0; ic < CC; ic++) {
        const float* ip = inb + ic * IH * IW;
        for (int i = tid; i < SR * SC; i += 256) {
            int sr = i / SC, scn = i % SC;
            int r = r0 + sr, cn = scn - 1;
            float v = 0.f;
            if (r >= 0 && r < IH && cn >= 0 && cn < IW) v = ip[r * IW + cn];
            sIn[i] = v;
        }
        if (tid < 128) {
            int oc = tid >> 4, k = tid & 15;
            sW[tid] = w[((ocg * 8 + oc) * CC + ic) * 16 + k];
        }
        __syncthreads();
#pragma unroll
        for (int ky = 0; ky < 4; ky++) {
#pragma unroll
            for (int kx = 0; kx < 4; kx++) {
                float v[PPT];
#pragma unroll
                for (int p = 0; p < PPT; p++)
                    v[p] = sIn[(2 * lr[p] + ky) * SC + 2 * lc[p] + kx];
#pragma unroll
                for (int oc = 0; oc < 8; oc++) {
                    float wv = sW[oc * 16 + ky * 4 + kx];
#pragma unroll
                    for (int p = 0; p < PPT; p++) acc[oc][p] += wv * v[p];
                }
            }
        }
        __syncthreads();
    }
#pragma unroll
    for (int oc = 0; oc < 8; oc++)
#pragma unroll
        for (int p = 0; p < PPT; p++)
            out[((b * CC + ocg * 8 + oc) * OH + ty0 + lr[p]) * OW + lc[p]] =
                acc[oc][p];
}

// ---------------- ODE conv 3x3 pad1: 65 in-ch (ch0 = const time) -----------
// mode 0: out=v   (u = first rhs conv)
// mode 1: out=v, ka=v          (k1)
// mode 2: out=v, ka+=2v        (k2,k3)
// mode 3: z += DT/6*(ka+v)     (k4)
__global__ __launch_bounds__(256)
void conv3x3_k(const float* __restrict__ in, const float* __restrict__ w,
               const float* __restrict__ bias, float t, int mode,
               float* __restrict__ out, float* __restrict__ ka,
               float* __restrict__ z) {
    __shared__ float sW[8 * 65 * 9];   // 18.7KB
    __shared__ float sIn[34 * 34];     //  4.6KB
    int ocg = blockIdx.x, b = blockIdx.y;
    int tid = threadIdx.x;
    int tx = tid & 31, ty = tid >> 5;

    for (int i = tid; i < 8 * 65 * 9; i += 256)
        sW[i] = w[ocg * 8 * 585 + i];
    __syncthreads();

    float acc[8][4];
#pragma unroll
    for (int oc = 0; oc < 8; oc++) {
        float bv = bias[ocg * 8 + oc];
#pragma unroll
        for (int p = 0; p < 4; p++) acc[oc][p] = bv;
    }
    // time channel (channel 0) with zero padding at borders
#pragma unroll
    for (int p = 0; p < 4; p++) {
        int r = ty + 8 * p;
#pragma unroll
        for (int ky = 0; ky < 3; ky++) {
            int rr = r + ky - 1;
            if (rr < 0 || rr >= 32) continue;
#pragma unroll
            for (int kx = 0; kx < 3; kx++) {
                int cn = tx + kx - 1;
                if (cn < 0 || cn >= 32) continue;
#pragma unroll
                for (int oc = 0; oc < 8; oc++)
                    acc[oc][p] += t * sW[oc * 585 + ky * 3 + kx];
            }
        }
    }

    const float* inb = in + (b * CC) * 1024;
    for (int ic = 0; ic < CC; ic++) {
        const float* ip = inb + ic * 1024;
        for (int i = tid; i < 34 * 34; i += 256) {
            int sr = i / 34, scn = i % 34;
            int r = sr - 1, cn = scn - 1;
            sIn[i] = (r >= 0 && r < 32 && cn >= 0 && cn < 32) ? ip[r * 32 + cn]
                                                              : 0.f;
        }
        __syncthreads();
        const float* wic = sW + (ic + 1) * 9;
#pragma unroll
        for (int ky = 0; ky < 3; ky++) {
#pragma unroll
            for (int kx = 0; kx < 3; kx++) {
                float v[4];
#pragma unroll
                for (int p = 0; p < 4; p++)
                    v[p] = sIn[(ty + 8 * p + ky) * 34 + tx + kx];
#pragma unroll
                for (int oc = 0; oc < 8; oc++) {
                    float wv = wic[oc * 585 + ky * 3 + kx];
#pragma unroll
                    for (int p = 0; p < 4; p++) acc[oc][p] += wv * v[p];
                }
            }
        }
        __syncthreads();
    }
#pragma unroll
    for (int oc = 0; oc < 8; oc++) {
#pragma unroll
        for (int p = 0; p < 4; p++) {
            int idx = (b * CC + ocg * 8 + oc) * 1024 + (ty + 8 * p) * 32 + tx;
            float v = acc[oc][p];
            if (mode == 0) {
                out[idx] = v;
            } else if (mode == 1) {
                out[idx] = v;
                ka[idx] = v;
            } else if (mode == 2) {
                out[idx] = v;
                ka[idx] += 2.f * v;
            } else {
                z[idx] += DT6 * (ka[idx] + v);
            }
        }
    }
}

// ---------------- head: GN + ReLU + global-avg-pool ------------------------
__global__ __launch_bounds__(256)
void gn_pool_k(const float* __restrict__ in, const float* __restrict__ gw,
               const float* __restrict__ gb, float* __restrict__ pool) {
    int bc = blockIdx.x;
    int c = bc & (CC - 1);
    const float* ip = in + bc * 1024;
    float s = 0.f, ss = 0.f;
    for (int i = threadIdx.x; i < 1024; i += 256) {
        float v = ip[i];
        s += v; ss += v * v;
    }
#pragma unroll
    for (int o = 16; o > 0; o >>= 1) {
        s  += __shfl_xor_sync(~0u, s, o);
        ss += __shfl_xor_sync(~0u, ss, o);
    }
    __shared__ float rs[8], rss[8];
    __shared__ float sh_sc, sh_sf;
    int wid = threadIdx.x >> 5, lid = threadIdx.x & 31;
    if (lid == 0) { rs[wid] = s; rss[wid] = ss; }
    __syncthreads();
    if (threadIdx.x == 0) {
        float S = 0.f, SS = 0.f;
#pragma unroll
        for (int i = 0; i < 8; i++) { S += rs[i]; SS += rss[i]; }
        float m = S / 1024.f;
        float var = SS / 1024.f - m * m;
        float sc = gw[c] * rsqrtf(var + 1e-5f);
        sh_sc = sc;
        sh_sf = gb[c] - m * sc;
    }
    __syncthreads();
    float sc = sh_sc, sf = sh_sf;
    float a = 0.f;
    for (int i = threadIdx.x; i < 1024; i += 256)
        a += fmaxf(ip[i] * sc + sf, 0.f);
#pragma unroll
    for (int o = 16; o > 0; o >>= 1) a += __shfl_xor_sync(~0u, a, o);
    if (lid == 0) rs[wid] = a;
    __syncthreads();
    if (threadIdx.x == 0) {
        float S = 0.f;
#pragma unroll
        for (int i = 0; i < 8; i++) S += rs[i];
        pool[bc] = S / 1024.f;
    }
}

__global__ __launch_bounds__(256)
void linear_k(const float* __restrict__ pool, const float* __restrict__ W,
              const float* __restrict__ bias, float* __restrict__ out) {
    int idx = blockIdx.x * 256 + threadIdx.x;
    if (idx >= BB * 10) return;
    int b = idx / 10, n = idx % 10;
    float acc = bias[n];
#pragma unroll 8
    for (int c = 0; c < CC; c++) acc += pool[b * CC + c] * W[n * CC + c];
    out[idx] = acc;
}

// ---------------- launch ----------------------------------------------------
extern "C" void kernel_launch(void* const* d_in, const int* in_sizes, int n_in,
                              void* d_out, int out_size) {
    const float* x      = (const float*)d_in[0];
    const float* ds_w1  = (const float*)d_in[1];
    const float* ds_b1  = (const float*)d_in[2];
    const float* ds_n1w = (const float*)d_in[3];
    const float* ds_n1b = (const float*)d_in[4];
    const float* ds_w2  = (const float*)d_in[5];
    const float* ds_b2  = (const float*)d_in[6];
    const float* ds_n2w = (const float*)d_in[7];
    const float* ds_n2b = (const float*)d_in[8];
    const float* ds_w3  = (const float*)d_in[9];
    const float* ds_b3  = (const float*)d_in[10];
    const float* ode_w1 = (const float*)d_in[11];
    const float* ode_b1 = (const float*)d_in[12];
    const float* ode_n1w= (const float*)d_in[13];
    const float* ode_n1b= (const float*)d_in[14];
    const float* ode_w2 = (const float*)d_in[15];
    const float* ode_b2 = (const float*)d_in[16];
    const float* ode_n2w= (const float*)d_in[17];
    const float* ode_n2b= (const float*)d_in[18];
    const float* head_nw= (const float*)d_in[19];
    const float* head_nb= (const float*)d_in[20];
    const float* head_W = (const float*)d_in[21];
    const float* head_b = (const float*)d_in[22];
    float* out = (float*)d_out;

    float *h1, *h2, *z, *g, *u, *kb, *ka, *pool;
    cudaGetSymbolAddress((void**)&h1, g_h1);
    cudaGetSymbolAddress((void**)&h2, g_h2);
    cudaGetSymbolAddress((void**)&z,  g_z);
    cudaGetSymbolAddress((void**)&g,  g_g);
    cudaGetSymbolAddress((void**)&u,  g_u);
    cudaGetSymbolAddress((void**)&kb, g_kb);
    cudaGetSymbolAddress((void**)&ka, g_ka);
    cudaGetSymbolAddress((void**)&pool, g_pool);

    // ---- downsampler ----
    conv1_k<<<dim3(64, 64, 64), 256>>>(x, ds_w1, ds_b1);
    gn_relu_k<16384><<<BB * CC, 256>>>(h1, h1, 0.f, ds_n1w, ds_n1b, h1);
    conv4_k<128, 128, 64, 64, 16><<<dim3(4, 8, 64), 256>>>(h1, ds_w2, ds_b2, h2);
    gn_relu_k<4096><<<BB * CC, 256>>>(h2, h2, 0.f, ds_n2w, ds_n2b, h2);
    conv4_k<64, 64, 32, 32, 32><<<dim3(1, 8, 64), 256>>>(h2, ds_w3, ds_b3, z);

    // ---- ODE: 10 RK4 steps ----
    dim3 cgrid(8, 64);
    for (int i = 0; i < 10; i++) {
        float t = (float)i * 0.1f;
        // k1
        gn_relu_k<1024><<<BB * CC, 256>>>(z, z, 0.f, ode_n1w, ode_n1b, g);
        conv3x3_k<<<cgrid, 256>>>(g, ode_w1, ode_b1, t, 0, u, ka, z);
        gn_relu_k<1024><<<BB * CC, 256>>>(u, u, 0.f, ode_n2w, ode_n2b, g);
        conv3x3_k<<<cgrid, 256>>>(g, ode_w2, ode_b2, t, 1, kb, ka, z);
        // k2
        gn_relu_k<1024><<<BB * CC, 256>>>(z, kb, 0.05f, ode_n1w, ode_n1b, g);
        conv3x3_k<<<cgrid, 256>>>(g, ode_w1, ode_b1, t + 0.05f, 0, u, ka, z);
        gn_relu_k<1024><<<BB * CC, 256>>>(u, u, 0.f, ode_n2w, ode_n2b, g);
        conv3x3_k<<<cgrid, 256>>>(g, ode_w2, ode_b2, t + 0.05f, 2, kb, ka, z);
        // k3
        gn_relu_k<1024><<<BB * CC, 256>>>(z, kb, 0.05f, ode_n1w, ode_n1b, g);
        conv3x3_k<<<cgrid, 256>>>(g, ode_w1, ode_b1, t + 0.05f, 0, u, ka, z);
        gn_relu_k<1024><<<BB * CC, 256>>>(u, u, 0.f, ode_n2w, ode_n2b, g);
        conv3x3_k<<<cgrid, 256>>>(g, ode_w2, ode_b2, t + 0.05f, 2, kb, ka, z);
        // k4
        gn_relu_k<1024><<<BB * CC, 256>>>(z, kb, 0.1f, ode_n1w, ode_n1b, g);
        conv3x3_k<<<cgrid, 256>>>(g, ode_w1, ode_b1, t + 0.1f, 0, u, ka, z);
        gn_relu_k<1024><<<BB * CC, 256>>>(u, u, 0.f, ode_n2w, ode_n2b, g);
        conv3x3_k<<<cgrid, 256>>>(g, ode_w2, ode_b2, t + 0.1f, 3, kb, ka, z);
    }

    // ---- head ----
    gn_pool_k<<<BB * CC, 256>>>(z, head_nw, head_nb, pool);
    linear_k<<<(BB * 10 + 255) / 256, 256>>>(pool, head_W, head_b, out);
}

// round 2
// speedup vs baseline: 1.0020x; 1.0020x over previous
#include <cuda_runtime.h>

#define BB 64
#define CC 64
#define DT6 (0.1f/6.0f)

// ---------------- scratch (device globals; no allocation allowed) ----------
static __device__ float g_h1[BB*CC*128*128];  // 268MB
static __device__ float g_h2[BB*CC*64*64];    // 67MB
static __device__ float g_z [BB*CC*32*32];
static __device__ float g_g [BB*CC*32*32];
static __device__ float g_u [BB*CC*32*32];
static __device__ float g_kb[BB*CC*32*32];
static __device__ float g_ka[BB*CC*32*32];
static __device__ float g_pool[BB*CC];

// ---------------- conv1: 1->64, 3x3 VALID, 130x130 -> 128x128 --------------
__global__ __launch_bounds__(256)
void conv1_k(const float* __restrict__ x, const float* __restrict__ w,
             const float* __restrict__ bias) {
    int oc = blockIdx.y, b = blockIdx.z;
    int pix = blockIdx.x * 256 + threadIdx.x;
    int oy = pix >> 7, ox = pix & 127;
    const float* xp = x + (b * 130 + oy) * 130 + ox;
    const float* wp = w + oc * 9;
    float acc = bias[oc];
#pragma unroll
    for (int ky = 0; ky < 3; ky++)
#pragma unroll
        for (int kx = 0; kx < 3; kx++)
            acc += xp[ky * 130 + kx] * __ldg(wp + ky * 3 + kx);
    g_h1[((b * CC + oc) * 128 + oy) * 128 + ox] = acc;
}

// ---------------- GroupNorm(C,C) + ReLU, input = in + alpha*kin ------------
template <int N>
__global__ __launch_bounds__(256)
void gn_relu_k(const float* __restrict__ in, const float* __restrict__ kin,
               float alpha, const float* __restrict__ gw,
               const float* __restrict__ gb, float* __restrict__ out) {
    int bc = blockIdx.x;
    int c = bc & (CC - 1);
    int off = bc * N;
    const float* ip = in + off;
    const float* kp = kin + off;
    float s = 0.f, ss = 0.f;
    for (int i = threadIdx.x; i < N; i += 256) {
        float v = ip[i] + alpha * kp[i];
        s += v; ss += v * v;
    }
#pragma unroll
    for (int o = 16; o > 0; o >>= 1) {
        s  += __shfl_xor_sync(~0u, s, o);
        ss += __shfl_xor_sync(~0u, ss, o);
    }
    __shared__ float rs[8], rss[8];
    __shared__ float sh_sc, sh_sf;
    int wid = threadIdx.x >> 5, lid = threadIdx.x & 31;
    if (lid == 0) { rs[wid] = s; rss[wid] = ss; }
    __syncthreads();
    if (threadIdx.x == 0) {
        float S = 0.f, SS = 0.f;
#pragma unroll
        for (int i = 0; i < 8; i++) { S += rs[i]; SS += rss[i]; }
        float m = S / (float)N;
        float var = SS / (float)N - m * m;
        float sc = gw[c] * rsqrtf(var + 1e-5f);
        sh_sc = sc;
        sh_sf = gb[c] - m * sc;
    }
    __syncthreads();
    float sc = sh_sc, sf = sh_sf;
    for (int i = threadIdx.x; i < N; i += 256) {
        float v = ip[i] + alpha * kp[i];
        out[off + i] = fmaxf(v * sc + sf, 0.f);
    }
}

// ---------------- conv 4x4 stride2 pad1 (64->64 ch) ------------------------
template <int IH, int IW, int OH, int OW, int TH>
__global__ __launch_bounds__(256)
void conv4_k(const float* __restrict__ in, const float* __restrict__ w,
             const float* __restrict__ bias, float* __restrict__ out) {
    constexpr int SR = 2 * TH + 2, SC = IW + 2;
    constexpr int PPT = TH * OW / 256;
    __shared__ float sIn[SR * SC];
    __shared__ float sW[128];
    int tile = blockIdx.x, ocg = blockIdx.y, b = blockIdx.z;
    int ty0 = tile * TH;
    int tid = threadIdx.x;

    int lr[PPT], lc[PPT];
    float acc[8][PPT];
#pragma unroll
    for (int p = 0; p < PPT; p++) {
        int px = tid + 256 * p;
        lr[p] = px / OW;
        lc[p] = px % OW;
    }
#pragma unroll
    for (int oc = 0; oc < 8; oc++) {
        float bv = bias[ocg * 8 + oc];
#pragma unroll
        for (int p = 0; p < PPT; p++) acc[oc][p] = bv;
    }
    const float* inb = in + (b * CC) * IH * IW;
    int r0 = 2 * ty0 - 1;
    for (int ic = 0; ic < CC; ic++) {
        const float* ip = inb + ic * IH * IW;
        for (int i = tid; i < SR * SC; i += 256) {
            int sr = i / SC, scn = i % SC;
            int r = r0 + sr, cn = scn - 1;
            float v = 0.f;
            if (r >= 0 && r < IH && cn >= 0 && cn < IW) v = ip[r * IW + cn];
            sIn[i] = v;
        }
        if (tid < 128) {
            int oc = tid >> 4, k = tid & 15;
            sW[tid] = w[((ocg * 8 + oc) * CC + ic) * 16 + k];
        }
        __syncthreads();
#pragma unroll
        for (int ky = 0; ky < 4; ky++) {
#pragma unroll
            for (int kx = 0; kx < 4; kx++) {
                float v[PPT];
#pragma unroll
                for (int p = 0; p < PPT; p++)
                    v[p] = sIn[(2 * lr[p] + ky) * SC + 2 * lc[p] + kx];
#pragma unroll
                for (int oc = 0; oc < 8; oc++) {
                    float wv = sW[oc * 16 + ky * 4 + kx];
#pragma unroll
                    for (int p = 0; p < PPT; p++) acc[oc][p] += wv * v[p];
                }
            }
        }
        __syncthreads();
    }
#pragma unroll
    for (int oc = 0; oc < 8; oc++)
#pragma unroll
        for (int p = 0; p < PPT; p++)
            out[((b * CC + ocg * 8 + oc) * OH + ty0 + lr[p]) * OW + lc[p]] =
                acc[oc][p];
}

// ---------------- ODE conv 3x3 pad1: 65 in-ch (ch0 = const time) -----------
// mode 0: out=v   (u = first rhs conv)
// mode 1: out=v, ka=v          (k1)
// mode 2: out=v, ka+=2v        (k2,k3)
// mode 3: z += DT/6*(ka+v)     (k4)
__global__ __launch_bounds__(256)
void conv3x3_k(const float* __restrict__ in, const float* __restrict__ w,
               const float* __restrict__ bias, float t, int mode,
               float* __restrict__ out, float* __restrict__ ka,
               float* __restrict__ z) {
    __shared__ float sW[8 * 65 * 9];   // 18.7KB
    __shared__ float sIn[34 * 34];     //  4.6KB
    int ocg = blockIdx.x, b = blockIdx.y;
    int tid = threadIdx.x;
    int tx = tid & 31, ty = tid >> 5;

    for (int i = tid; i < 8 * 65 * 9; i += 256)
        sW[i] = w[ocg * 8 * 585 + i];
    __syncthreads();

    float acc[8][4];
#pragma unroll
    for (int oc = 0; oc < 8; oc++) {
        float bv = bias[ocg * 8 + oc];
#pragma unroll
        for (int p = 0; p < 4; p++) acc[oc][p] = bv;
    }
    // time channel (channel 0) with zero padding at borders
#pragma unroll
    for (int p = 0; p < 4; p++) {
        int r = ty + 8 * p;
#pragma unroll
        for (int ky = 0; ky < 3; ky++) {
            int rr = r + ky - 1;
            if (rr < 0 || rr >= 32) continue;
#pragma unroll
            for (int kx = 0; kx < 3; kx++) {
                int cn = tx + kx - 1;
                if (cn < 0 || cn >= 32) continue;
#pragma unroll
                for (int oc = 0; oc < 8; oc++)
                    acc[oc][p] += t * sW[oc * 585 + ky * 3 + kx];
            }
        }
    }

    const float* inb = in + (b * CC) * 1024;
    for (int ic = 0; ic < CC; ic++) {
        const float* ip = inb + ic * 1024;
        for (int i = tid; i < 34 * 34; i += 256) {
            int sr = i / 34, scn = i % 34;
            int r = sr - 1, cn = scn - 1;
            sIn[i] = (r >= 0 && r < 32 && cn >= 0 && cn < 32) ? ip[r * 32 + cn]
                                                              : 0.f;
        }
        __syncthreads();
        const float* wic = sW + (ic + 1) * 9;
#pragma unroll
        for (int ky = 0; ky < 3; ky++) {
#pragma unroll
            for (int kx = 0; kx < 3; kx++) {
                float v[4];
#pragma unroll
                for (int p = 0; p < 4; p++)
                    v[p] = sIn[(ty + 8 * p + ky) * 34 + tx + kx];
#pragma unroll
                for (int oc = 0; oc < 8; oc++) {
                    float wv = wic[oc * 585 + ky * 3 + kx];
#pragma unroll
                    for (int p = 0; p < 4; p++) acc[oc][p] += wv * v[p];
                }
            }
        }
        __syncthreads();
    }
#pragma unroll
    for (int oc = 0; oc < 8; oc++) {
#pragma unroll
        for (int p = 0; p < 4; p++) {
            int idx = (b * CC + ocg * 8 + oc) * 1024 + (ty + 8 * p) * 32 + tx;
            float v = acc[oc][p];
            if (mode == 0) {
                out[idx] = v;
            } else if (mode == 1) {
                out[idx] = v;
                ka[idx] = v;
            } else if (mode == 2) {
                out[idx] = v;
                ka[idx] += 2.f * v;
            } else {
                z[idx] += DT6 * (ka[idx] + v);
            }
        }
    }
}

// ---------------- head: GN + ReLU + global-avg-pool ------------------------
__global__ __launch_bounds__(256)
void gn_pool_k(const float* __restrict__ in, const float* __restrict__ gw,
               const float* __restrict__ gb, float* __restrict__ pool) {
    int bc = blockIdx.x;
    int c = bc & (CC - 1);
    const float* ip = in + bc * 1024;
    float s = 0.f, ss = 0.f;
    for (int i = threadIdx.x; i < 1024; i += 256) {
        float v = ip[i];
        s += v; ss += v * v;
    }
#pragma unroll
    for (int o = 16; o > 0; o >>= 1) {
        s  += __shfl_xor_sync(~0u, s, o);
        ss += __shfl_xor_sync(~0u, ss, o);
    }
    __shared__ float rs[8], rss[8];
    __shared__ float sh_sc, sh_sf;
    int wid = threadIdx.x >> 5, lid = threadIdx.x & 31;
    if (lid == 0) { rs[wid] = s; rss[wid] = ss; }
    __syncthreads();
    if (threadIdx.x == 0) {
        float S = 0.f, SS = 0.f;
#pragma unroll
        for (int i = 0; i < 8; i++) { S += rs[i]; SS += rss[i]; }
        float m = S / 1024.f;
        float var = SS / 1024.f - m * m;
        float sc = gw[c] * rsqrtf(var + 1e-5f);
        sh_sc = sc;
        sh_sf = gb[c] - m * sc;
    }
    __syncthreads();
    float sc = sh_sc, sf = sh_sf;
    float a = 0.f;
    for (int i = threadIdx.x; i < 1024; i += 256)
        a += fmaxf(ip[i] * sc + sf, 0.f);
#pragma unroll
    for (int o = 16; o > 0; o >>= 1) a += __shfl_xor_sync(~0u, a, o);
    if (lid == 0) rs[wid] = a;
    __syncthreads();
    if (threadIdx.x == 0) {
        float S = 0.f;
#pragma unroll
        for (int i = 0; i < 8; i++) S += rs[i];
        pool[bc] = S / 1024.f;
    }
}

__global__ __launch_bounds__(256)
void linear_k(const float* __restrict__ pool, const float* __restrict__ W,
              const float* __restrict__ bias, float* __restrict__ out) {
    int idx = blockIdx.x * 256 + threadIdx.x;
    if (idx >= BB * 10) return;
    int b = idx / 10, n = idx % 10;
    float acc = bias[n];
#pragma unroll 8
    for (int c = 0; c < CC; c++) acc += pool[b * CC + c] * W[n * CC + c];
    out[idx] = acc;
}

// ---------------- launch ----------------------------------------------------
extern "C" void kernel_launch(void* const* d_in, const int* in_sizes, int n_in,
                              void* d_out, int out_size) {
    const float* x      = (const float*)d_in[0];
    const float* ds_w1  = (const float*)d_in[1];
    const float* ds_b1  = (const float*)d_in[2];
    const float* ds_n1w = (const float*)d_in[3];
    const float* ds_n1b = (const float*)d_in[4];
    const float* ds_w2  = (const float*)d_in[5];
    const float* ds_b2  = (const float*)d_in[6];
    const float* ds_n2w = (const float*)d_in[7];
    const float* ds_n2b = (const float*)d_in[8];
    const float* ds_w3  = (const float*)d_in[9];
    const float* ds_b3  = (const float*)d_in[10];
    const float* ode_w1 = (const float*)d_in[11];
    const float* ode_b1 = (const float*)d_in[12];
    const float* ode_n1w= (const float*)d_in[13];
    const float* ode_n1b= (const float*)d_in[14];
    const float* ode_w2 = (const float*)d_in[15];
    const float* ode_b2 = (const float*)d_in[16];
    const float* ode_n2w= (const float*)d_in[17];
    const float* ode_n2b= (const float*)d_in[18];
    const float* head_nw= (const float*)d_in[19];
    const float* head_nb= (const float*)d_in[20];
    const float* head_W = (const float*)d_in[21];
    const float* head_b = (const float*)d_in[22];
    float* out = (float*)d_out;

    float *h1, *h2, *z, *g, *u, *kb, *ka, *pool;
    cudaGetSymbolAddress((void**)&h1, g_h1);
    cudaGetSymbolAddress((void**)&h2, g_h2);
    cudaGetSymbolAddress((void**)&z,  g_z);
    cudaGetSymbolAddress((void**)&g,  g_g);
    cudaGetSymbolAddress((void**)&u,  g_u);
    cudaGetSymbolAddress((void**)&kb, g_kb);
    cudaGetSymbolAddress((void**)&ka, g_ka);
    cudaGetSymbolAddress((void**)&pool, g_pool);

    // ---- downsampler ----
    conv1_k<<<dim3(64, 64, 64), 256>>>(x, ds_w1, ds_b1);
    gn_relu_k<16384><<<BB * CC, 256>>>(h1, h1, 0.f, ds_n1w, ds_n1b, h1);
    conv4_k<128, 128, 64, 64, 16><<<dim3(4, 8, 64), 256>>>(h1, ds_w2, ds_b2, h2);
    gn_relu_k<4096><<<BB * CC, 256>>>(h2, h2, 0.f, ds_n2w, ds_n2b, h2);
    conv4_k<64, 64, 32, 32, 32><<<dim3(1, 8, 64), 256>>>(h2, ds_w3, ds_b3, z);

    // ---- ODE: 10 RK4 steps ----
    dim3 cgrid(8, 64);
    for (int i = 0; i < 10; i++) {
        float t = (float)i * 0.1f;
        // k1
        gn_relu_k<1024><<<BB * CC, 256>>>(z, z, 0.f, ode_n1w, ode_n1b, g);
        conv3x3_k<<<cgrid, 256>>>(g, ode_w1, ode_b1, t, 0, u, ka, z);
        gn_relu_k<1024><<<BB * CC, 256>>>(u, u, 0.f, ode_n2w, ode_n2b, g);
        conv3x3_k<<<cgrid, 256>>>(g, ode_w2, ode_b2, t, 1, kb, ka, z);
        // k2
        gn_relu_k<1024><<<BB * CC, 256>>>(z, kb, 0.05f, ode_n1w, ode_n1b, g);
        conv3x3_k<<<cgrid, 256>>>(g, ode_w1, ode_b1, t + 0.05f, 0, u, ka, z);
        gn_relu_k<1024><<<BB * CC, 256>>>(u, u, 0.f, ode_n2w, ode_n2b, g);
        conv3x3_k<<<cgrid, 256>>>(g, ode_w2, ode_b2, t + 0.05f, 2, kb, ka, z);
        // k3
        gn_relu_k<1024><<<BB * CC, 256>>>(z, kb, 0.05f, ode_n1w, ode_n1b, g);
        conv3x3_k<<<cgrid, 256>>>(g, ode_w1, ode_b1, t + 0.05f, 0, u, ka, z);
        gn_relu_k<1024><<<BB * CC, 256>>>(u, u, 0.f, ode_n2w, ode_n2b, g);
        conv3x3_k<<<cgrid, 256>>>(g, ode_w2, ode_b2, t + 0.05f, 2, kb, ka, z);
        // k4
        gn_relu_k<1024><<<BB * CC, 256>>>(z, kb, 0.1f, ode_n1w, ode_n1b, g);
        conv3x3_k<<<cgrid, 256>>>(g, ode_w1, ode_b1, t + 0.1f, 0, u, ka, z);
        gn_relu_k<1024><<<BB * CC, 256>>>(u, u, 0.f, ode_n2w, ode_n2b, g);
        conv3x3_k<<<cgrid, 256>>>(g, ode_w2, ode_b2, t + 0.1f, 3, kb, ka, z);
    }

    // ---- head ----
    gn_pool_k<<<BB * CC, 256>>>(z, head_nw, head_nb, pool);
    linear_k<<<(BB * 10 + 255) / 256, 256>>>(pool, head_W, head_b, out);
}

// round 4
// speedup vs baseline: 3.8379x; 3.8302x over previous
#include <cuda_runtime.h>
#include <cuda_fp16.h>
#include <cstdint>

#define BB 64
#define CC 64
#define DT6 (0.1f/6.0f)

// ---------------- scratch (device globals) ---------------------------------
static __device__ float g_h1[BB*CC*128*128];
static __device__ float g_h2[BB*CC*64*64];
static __device__ float g_z [BB*CC*1024];        // NHWC fp32 [b][y][x][c]
static __device__ float g_u [BB*CC*1024];        // NHWC fp32
static __device__ float g_kb[BB*CC*1024];        // NHWC fp32
static __device__ float g_ka[BB*CC*1024];        // NHWC fp32
static __device__ __half g_g[BB*CC*1024];        // NHWC fp16 (conv input)
static __device__ float g_pool[BB*CC];
static __device__ __half g_BpackH[36*64*32];     // [cv*18 + s9*2+h][oc][k]
static __device__ float g_Wcls[2*3*3*64];        // time-channel sums per border class

// ---------------- fp16 MMA -------------------------------------------------
__device__ __forceinline__ void mma_f16(float* c, uint32_t a0, uint32_t a1,
                                        uint32_t a2, uint32_t a3,
                                        uint32_t b0, uint32_t b1) {
    asm volatile(
        "mma.sync.aligned.m16n8k16.row.col.f32.f16.f16.f32 "
        "{%0,%1,%2,%3},{%4,%5,%6,%7},{%8,%9},{%0,%1,%2,%3};"
        : "+f"(c[0]), "+f"(c[1]), "+f"(c[2]), "+f"(c[3])
        : "r"(a0), "r"(a1), "r"(a2), "r"(a3), "r"(b0), "r"(b1));
}

// ---------------- weight prepack -------------------------------------------
__global__ __launch_bounds__(256)
void prep_w(const float* __restrict__ w1, const float* __restrict__ w2) {
    int i = blockIdx.x * 256 + threadIdx.x;
    if (i < 36 * 2048) {
        int k = i & 31;
        int oc = (i >> 5) & 63;
        int tix = i >> 11;
        int h = tix & 1, s9 = (tix >> 1) % 9, cv = tix / 18;
        int dy = s9 / 3, dx = s9 % 3;
        const float* w = cv ? w2 : w1;
        int icg = h * 32 + k;
        g_BpackH[i] = __float2half(w[((oc * 65 + icg + 1) * 3 + dy) * 3 + dx]);
    }
    if (i < 2 * 3 * 3 * 64) {
        int oc = i & 63;
        int t2 = i >> 6;
        int xs = t2 % 3, ys = (t2 / 3) % 3, cv = t2 / 9;
        const float* w = cv ? w2 : w1;
        float s = 0.f;
        for (int dy = 0; dy < 3; dy++)
            for (int dx = 0; dx < 3; dx++) {
                bool okY = !((ys == 0 && dy == 0) || (ys == 2 && dy == 2));
                bool okX = !((xs == 0 && dx == 0) || (xs == 2 && dx == 2));
                if (okY && okX) s += w[(oc * 65 * 3 + dy) * 3 + dx];
            }
        g_Wcls[((cv * 3 + ys) * 3 + xs) * 64 + oc] = s;
    }
}

// ---------------- HMMA ODE conv 3x3 pad1 ------------------------------------
// CTA (q,b): 128 px (y = 4q+warp, x = 0..31) x 64 oc. A direct from global fp16
// NHWC, B from prepacked weights. MODE 0: out=v ; 1: out=v, ka=v ;
// 2: out=v, ka+=2v ; 3: z += DT6*(ka+v)
template <int MODE>
__global__ __launch_bounds__(128)
void ode_conv_mma(const __half* __restrict__ g, const __half* __restrict__ wpk,
                  float t, const float* __restrict__ bias,
                  const float* __restrict__ wcls,
                  float* __restrict__ out, float* __restrict__ ka,
                  float* __restrict__ z) {
    int q = blockIdx.x, b = blockIdx.y;
    int w = threadIdx.x >> 5, lane = threadIdx.x & 31;
    int gid = lane >> 2, tig = lane & 3;
    int y = 4 * q + w;

    float acc[2][8][4];
#pragma unroll
    for (int mt = 0; mt < 2; mt++)
#pragma unroll
        for (int nt = 0; nt < 8; nt++)
#pragma unroll
            for (int j = 0; j < 4; j++) acc[mt][nt][j] = 0.f;

    const __half* gb = g + (size_t)b * 65536;

#pragma unroll
    for (int c = 0; c < 18; c++) {
        int s9 = c >> 1, h = c & 1;
        int dy = s9 / 3, dx = s9 % 3;
        int yy = y + dy - 1;
        bool yok = (yy >= 0) && (yy < 32);
        const __half* rowp = gb + ((size_t)yy * 32) * 64 + h * 32;
        const __half* wp = wpk + c * 2048;

        // x coords for this thread's A rows (4 distinct x per mt pair)
        int xA0 = gid + dx - 1;          // mt0 rows 0..7
        int xA1 = gid + 8 + dx - 1;      // mt0 rows 8..15
        int xA2 = gid + 16 + dx - 1;     // mt1 rows 0..7
        int xA3 = gid + 24 + dx - 1;     // mt1 rows 8..15
        bool ok0 = yok && (xA0 >= 0) && (xA0 < 32);
        bool ok1 = yok && (xA1 >= 0) && (xA1 < 32);
        bool ok2 = yok && (xA2 >= 0) && (xA2 < 32);
        bool ok3 = yok && (xA3 >= 0) && (xA3 < 32);

#pragma unroll
        for (int kk = 0; kk < 2; kk++) {
            int ic = kk * 16 + 2 * tig;
            uint32_t A[2][4];
            A[0][0] = ok0 ? *(const uint32_t*)(rowp + xA0 * 64 + ic) : 0u;
            A[0][1] = ok1 ? *(const uint32_t*)(rowp + xA1 * 64 + ic) : 0u;
            A[0][2] = ok0 ? *(const uint32_t*)(rowp + xA0 * 64 + ic + 8) : 0u;
            A[0][3] = ok1 ? *(const uint32_t*)(rowp + xA1 * 64 + ic + 8) : 0u;
            A[1][0] = ok2 ? *(const uint32_t*)(rowp + xA2 * 64 + ic) : 0u;
            A[1][1] = ok3 ? *(const uint32_t*)(rowp + xA3 * 64 + ic) : 0u;
            A[1][2] = ok2 ? *(const uint32_t*)(rowp + xA2 * 64 + ic + 8) : 0u;
            A[1][3] = ok3 ? *(const uint32_t*)(rowp + xA3 * 64 + ic + 8) : 0u;

#pragma unroll
            for (int nt = 0; nt < 8; nt++) {
                int oc = nt * 8 + gid;
                const __half* wb = wp + oc * 32 + kk * 16 + 2 * tig;
                uint32_t b0 = *(const uint32_t*)(wb);
                uint32_t b1 = *(const uint32_t*)(wb + 8);
                mma_f16(acc[0][nt], A[0][0], A[0][1], A[0][2], A[0][3], b0, b1);
                mma_f16(acc[1][nt], A[1][0], A[1][1], A[1][2], A[1][3], b0, b1);
            }
        }
    }

    // epilogue
    int ys = (y == 0) ? 0 : ((y == 31) ? 2 : 1);
    const float* wcy = wcls + ys * 3 * 64;
#pragma unroll
    for (int mt = 0; mt < 2; mt++) {
#pragma unroll
        for (int rr = 0; rr < 2; rr++) {
            int x = mt * 16 + gid + rr * 8;
            int xs = (x == 0) ? 0 : ((x == 31) ? 2 : 1);
            const float* wcx = wcy + xs * 64;
            size_t base = ((size_t)b * 1024 + y * 32 + x) * 64;
#pragma unroll
            for (int nt = 0; nt < 8; nt++) {
                int oc = nt * 8 + 2 * tig;
                float2 v;
                v.x = acc[mt][nt][rr * 2 + 0] + __ldg(bias + oc) + t * __ldg(wcx + oc);
                v.y = acc[mt][nt][rr * 2 + 1] + __ldg(bias + oc + 1) + t * __ldg(wcx + oc + 1);
                if (MODE == 0) {
                    *(float2*)(out + base + oc) = v;
                } else if (MODE == 1) {
                    *(float2*)(out + base + oc) = v;
                    *(float2*)(ka + base + oc) = v;
                } else if (MODE == 2) {
                    *(float2*)(out + base + oc) = v;
                    float2 a = *(const float2*)(ka + base + oc);
                    a.x += 2.f * v.x; a.y += 2.f * v.y;
                    *(float2*)(ka + base + oc) = a;
                } else {
                    float2 a = *(const float2*)(ka + base + oc);
                    float2 zz = *(const float2*)(z + base + oc);
                    zz.x += DT6 * (a.x + v.x);
                    zz.y += DT6 * (a.y + v.y);
                    *(float2*)(z + base + oc) = zz;
                }
            }
        }
    }
}

// ---------------- GroupNorm + ReLU, NHWC, in + alpha*kin -> fp16 / pool ----
template <bool POOL>
__global__ __launch_bounds__(256)
void gn_nhwc(const float* __restrict__ in, const float* __restrict__ kin,
             float alpha, const float* __restrict__ gw,
             const float* __restrict__ gb, __half* __restrict__ out,
             float* __restrict__ pool) {
    int b = blockIdx.x, qtr = blockIdx.y;
    int tid = threadIdx.x;
    int cl = tid & 3;
    int c4 = qtr * 4 + cl;
    int gg = tid >> 2;
    const float4* ip = (const float4*)in + (size_t)b * 16384;
    const float4* kp = (const float4*)kin + (size_t)b * 16384;

    float4 s = {0, 0, 0, 0}, q2 = {0, 0, 0, 0};
#pragma unroll 4
    for (int i = 0; i < 16; i++) {
        int px = gg * 16 + i;
        float4 a = ip[px * 16 + c4];
        if (alpha != 0.f) {
            float4 k = kp[px * 16 + c4];
            a.x += alpha * k.x; a.y += alpha * k.y;
            a.z += alpha * k.z; a.w += alpha * k.w;
        }
        s.x += a.x; s.y += a.y; s.z += a.z; s.w += a.w;
        q2.x += a.x * a.x; q2.y += a.y * a.y; q2.z += a.z * a.z; q2.w += a.w * a.w;
    }
    __shared__ float4 shs[64][4], shq[64][4];
    __shared__ float4 shsc[4], shsf[4];
    shs[gg][cl] = s; shq[gg][cl] = q2;
    __syncthreads();
    if (tid < 4) {
        float4 S = {0, 0, 0, 0}, Q = {0, 0, 0, 0};
        for (int g2 = 0; g2 < 64; g2++) {
            float4 a = shs[g2][tid], c = shq[g2][tid];
            S.x += a.x; S.y += a.y; S.z += a.z; S.w += a.w;
            Q.x += c.x; Q.y += c.y; Q.z += c.z; Q.w += c.w;
        }
        float4 gw4 = ((const float4*)gw)[qtr * 4 + tid];
        float4 gb4 = ((const float4*)gb)[qtr * 4 + tid];
        float4 sc, sf;
        float m, var;
        m = S.x / 1024.f; var = Q.x / 1024.f - m * m; sc.x = gw4.x * rsqrtf(var + 1e-5f); sf.x = gb4.x - m * sc.x;
        m = S.y / 1024.f; var = Q.y / 1024.f - m * m; sc.y = gw4.y * rsqrtf(var + 1e-5f); sf.y = gb4.y - m * sc.y;
        m = S.z / 1024.f; var = Q.z / 1024.f - m * m; sc.z = gw4.z * rsqrtf(var + 1e-5f); sf.z = gb4.z - m * sc.z;
        m = S.w / 1024.f; var = Q.w / 1024.f - m * m; sc.w = gw4.w * rsqrtf(var + 1e-5f); sf.w = gb4.w - m * sc.w;
        shsc[tid] = sc; shsf[tid] = sf;
    }
    __syncthreads();
    float4 sc = shsc[cl], sf = shsf[cl];
    if (!POOL) {
        __half2* op = (__half2*)out + (size_t)b * 32768;
#pragma unroll 4
        for (int i = 0; i < 16; i++) {
            int px = gg * 16 + i;
            float4 a = ip[px * 16 + c4];
            if (alpha != 0.f) {
                float4 k = kp[px * 16 + c4];
                a.x += alpha * k.x; a.y += alpha * k.y;
                a.z += alpha * k.z; a.w += alpha * k.w;
            }
            float rx = fmaxf(a.x * sc.x + sf.x, 0.f);
            float ry = fmaxf(a.y * sc.y + sf.y, 0.f);
            float rz = fmaxf(a.z * sc.z + sf.z, 0.f);
            float rw = fmaxf(a.w * sc.w + sf.w, 0.f);
            op[px * 32 + c4 * 2 + 0] = __floats2half2_rn(rx, ry);
            op[px * 32 + c4 * 2 + 1] = __floats2half2_rn(rz, rw);
        }
    } else {
        float4 accp = {0, 0, 0, 0};
#pragma unroll 4
        for (int i = 0; i < 16; i++) {
            int px = gg * 16 + i;
            float4 a = ip[px * 16 + c4];
            accp.x += fmaxf(a.x * sc.x + sf.x, 0.f);
            accp.y += fmaxf(a.y * sc.y + sf.y, 0.f);
            accp.z += fmaxf(a.z * sc.z + sf.z, 0.f);
            accp.w += fmaxf(a.w * sc.w + sf.w, 0.f);
        }
        __syncthreads();
        shs[gg][cl] = accp;
        __syncthreads();
        if (tid < 4) {
            float4 S = {0, 0, 0, 0};
            for (int g2 = 0; g2 < 64; g2++) {
                float4 a = shs[g2][tid];
                S.x += a.x; S.y += a.y; S.z += a.z; S.w += a.w;
            }
            int c0 = (qtr * 4 + tid) * 4;
            pool[b * CC + c0 + 0] = S.x / 1024.f;
            pool[b * CC + c0 + 1] = S.y / 1024.f;
            pool[b * CC + c0 + 2] = S.z / 1024.f;
            pool[b * CC + c0 + 3] = S.w / 1024.f;
        }
    }
}

// ---------------- conv1: 1->64, 3x3 VALID, NCHW out -------------------------
__global__ __launch_bounds__(256)
void conv1_k(const float* __restrict__ x, const float* __restrict__ w,
             const float* __restrict__ bias) {
    int oc = blockIdx.y, b = blockIdx.z;
    int pix = blockIdx.x * 256 + threadIdx.x;
    int oy = pix >> 7, ox = pix & 127;
    const float* xp = x + (b * 130 + oy) * 130 + ox;
    const float* wp = w + oc * 9;
    float acc = bias[oc];
#pragma unroll
    for (int ky = 0; ky < 3; ky++)
#pragma unroll
        for (int kx = 0; kx < 3; kx++)
            acc += xp[ky * 130 + kx] * __ldg(wp + ky * 3 + kx);
    g_h1[((size_t)(b * CC + oc) * 128 + oy) * 128 + ox] = acc;
}

// ---------------- GN + ReLU NCHW (downsampler) ------------------------------
template <int N>
__global__ __launch_bounds__(256)
void gn_relu_k(const float* __restrict__ in, const float* __restrict__ gw,
               const float* __restrict__ gb, float* __restrict__ out) {
    int bc = blockIdx.x;
    int c = bc & (CC - 1);
    size_t off = (size_t)bc * N;
    const float* ip = in + off;
    float s = 0.f, ss = 0.f;
    for (int i = threadIdx.x; i < N; i += 256) {
        float v = ip[i];
        s += v; ss += v * v;
    }
#pragma unroll
    for (int o = 16; o > 0; o >>= 1) {
        s += __shfl_xor_sync(~0u, s, o);
        ss += __shfl_xor_sync(~0u, ss, o);
    }
    __shared__ float rs[8], rss[8];
    __shared__ float sh_sc, sh_sf;
    int wid = threadIdx.x >> 5, lid = threadIdx.x & 31;
    if (lid == 0) { rs[wid] = s; rss[wid] = ss; }
    __syncthreads();
    if (threadIdx.x == 0) {
        float S = 0.f, SS = 0.f;
#pragma unroll
        for (int i = 0; i < 8; i++) { S += rs[i]; SS += rss[i]; }
        float m = S / (float)N;
        float var = SS / (float)N - m * m;
        float sc = gw[c] * rsqrtf(var + 1e-5f);
        sh_sc = sc; sh_sf = gb[c] - m * sc;
    }
    __syncthreads();
    float sc = sh_sc, sf = sh_sf;
    for (int i = threadIdx.x; i < N; i += 256)
        out[off + i] = fmaxf(ip[i] * sc + sf, 0.f);
}

// ---------------- conv 4x4 stride2 pad1 (64->64 ch) -------------------------
template <int IH, int IW, int OH, int OW, int TH, int OUT_NHWC>
__global__ __launch_bounds__(256)
void conv4_k(const float* __restrict__ in, const float* __restrict__ w,
             const float* __restrict__ bias, float* __restrict__ out) {
    constexpr int SR = 2 * TH + 2, SC = IW + 2;
    constexpr int PPT = TH * OW / 256;
    __shared__ float sIn[SR * SC];
    __shared__ float sW[128];
    int tile = blockIdx.x, ocg = blockIdx.y, b = blockIdx.z;
    int ty0 = tile * TH;
    int tid = threadIdx.x;

    int lr[PPT], lc[PPT];
    float acc[8][PPT];
#pragma unroll
    for (int p = 0; p < PPT; p++) {
        int px = tid + 256 * p;
        lr[p] = px / OW;
        lc[p] = px % OW;
    }
#pragma unroll
    for (int oc = 0; oc < 8; oc++) {
        float bv = bias[ocg * 8 + oc];
#pragma unroll
        for (int p = 0; p < PPT; p++) acc[oc][p] = bv;
    }
    const float* inb = in + (size_t)(b * CC) * IH * IW;
    int r0 = 2 * ty0 - 1;
    for (int ic = 0; ic < CC; ic++) {
        const float* ip = inb + (size_t)ic * IH * IW;
        for (int i = tid; i < SR * SC; i += 256) {
            int sr = i / SC, scn = i % SC;
            int r = r0 + sr, cn = scn - 1;
            float v = 0.f;
            if (r >= 0 && r < IH && cn >= 0 && cn < IW) v = ip[r * IW + cn];
            sIn[i] = v;
        }
        if (tid < 128) {
            int oc = tid >> 4, k = tid & 15;
            sW[tid] = w[((ocg * 8 + oc) * CC + ic) * 16 + k];
        }
        __syncthreads();
#pragma unroll
        for (int ky = 0; ky < 4; ky++) {
#pragma unroll
            for (int kx = 0; kx < 4; kx++) {
                float v[PPT];
#pragma unroll
                for (int p = 0; p < PPT; p++)
                    v[p] = sIn[(2 * lr[p] + ky) * SC + 2 * lc[p] + kx];
#pragma unroll
                for (int oc = 0; oc < 8; oc++) {
                    float wv = sW[oc * 16 + ky * 4 + kx];
#pragma unroll
                    for (int p = 0; p < PPT; p++) acc[oc][p] += wv * v[p];
                }
            }
        }
        __syncthreads();
    }
#pragma unroll
    for (int oc = 0; oc < 8; oc++)
#pragma unroll
        for (int p = 0; p < PPT; p++) {
            if (OUT_NHWC)
                out[(((size_t)(b * OH + ty0 + lr[p]) * OW + lc[p]) * CC) + ocg * 8 + oc] = acc[oc][p];
            else
                out[((size_t)(b * CC + ocg * 8 + oc) * OH + ty0 + lr[p]) * OW + lc[p]] = acc[oc][p];
        }
}

// ---------------- head linear ------------------------------------------------
__global__ __launch_bounds__(256)
void linear_k(const float* __restrict__ pool, const float* __restrict__ W,
              const float* __restrict__ bias, float* __restrict__ out) {
    int idx = blockIdx.x * 256 + threadIdx.x;
    if (idx >= BB * 10) return;
    int b = idx / 10, n = idx % 10;
    float acc = bias[n];
#pragma unroll 8
    for (int c = 0; c < CC; c++) acc += pool[b * CC + c] * W[n * CC + c];
    out[idx] = acc;
}

// ---------------- launch ------------------------------------------------------
extern "C" void kernel_launch(void* const* d_in, const int* in_sizes, int n_in,
                              void* d_out, int out_size) {
    const float* x      = (const float*)d_in[0];
    const float* ds_w1  = (const float*)d_in[1];
    const float* ds_b1  = (const float*)d_in[2];
    const float* ds_n1w = (const float*)d_in[3];
    const float* ds_n1b = (const float*)d_in[4];
    const float* ds_w2  = (const float*)d_in[5];
    const float* ds_b2  = (const float*)d_in[6];
    const float* ds_n2w = (const float*)d_in[7];
    const float* ds_n2b = (const float*)d_in[8];
    const float* ds_w3  = (const float*)d_in[9];
    const float* ds_b3  = (const float*)d_in[10];
    const float* ode_w1 = (const float*)d_in[11];
    const float* ode_b1 = (const float*)d_in[12];
    const float* ode_n1w= (const float*)d_in[13];
    const float* ode_n1b= (const float*)d_in[14];
    const float* ode_w2 = (const float*)d_in[15];
    const float* ode_b2 = (const float*)d_in[16];
    const float* ode_n2w= (const float*)d_in[17];
    const float* ode_n2b= (const float*)d_in[18];
    const float* head_nw= (const float*)d_in[19];
    const float* head_nb= (const float*)d_in[20];
    const float* head_W = (const float*)d_in[21];
    const float* head_b = (const float*)d_in[22];
    float* out = (float*)d_out;

    float *h1, *h2, *z, *u, *kb, *ka, *pool, *wcls;
    __half *g, *bpk;
    cudaGetSymbolAddress((void**)&h1, g_h1);
    cudaGetSymbolAddress((void**)&h2, g_h2);
    cudaGetSymbolAddress((void**)&z,  g_z);
    cudaGetSymbolAddress((void**)&u,  g_u);
    cudaGetSymbolAddress((void**)&kb, g_kb);
    cudaGetSymbolAddress((void**)&ka, g_ka);
    cudaGetSymbolAddress((void**)&pool, g_pool);
    cudaGetSymbolAddress((void**)&g,  g_g);
    cudaGetSymbolAddress((void**)&bpk, g_BpackH);
    cudaGetSymbolAddress((void**)&wcls, g_Wcls);

    prep_w<<<288, 256>>>(ode_w1, ode_w2);

    // ---- downsampler ----
    conv1_k<<<dim3(64, 64, 64), 256>>>(x, ds_w1, ds_b1);
    gn_relu_k<16384><<<BB * CC, 256>>>(h1, ds_n1w, ds_n1b, h1);
    conv4_k<128, 128, 64, 64, 16, 0><<<dim3(4, 8, 64), 256>>>(h1, ds_w2, ds_b2, h2);
    gn_relu_k<4096><<<BB * CC, 256>>>(h2, ds_n2w, ds_n2b, h2);
    conv4_k<64, 64, 32, 32, 32, 1><<<dim3(1, 8, 64), 256>>>(h2, ds_w3, ds_b3, z);

    // ---- ODE: 10 RK4 steps (HMMA fp16 convs, NHWC) ----
    dim3 cgrid(8, 64), ggrid(64, 4);
    const __half* w1p = bpk;
    const __half* w2p = bpk + 18 * 2048;
    const float* wc1 = wcls;
    const float* wc2 = wcls + 9 * 64;
    for (int i = 0; i < 10; i++) {
        float t = (float)i * 0.1f;
        // k1
        gn_nhwc<false><<<ggrid, 256>>>(z, z, 0.f, ode_n1w, ode_n1b, g, nullptr);
        ode_conv_mma<0><<<cgrid, 128>>>(g, w1p, t, ode_b1, wc1, u, ka, z);
        gn_nhwc<false><<<ggrid, 256>>>(u, u, 0.f, ode_n2w, ode_n2b, g, nullptr);
        ode_conv_mma<1><<<cgrid, 128>>>(g, w2p, t, ode_b2, wc2, kb, ka, z);
        // k2
        gn_nhwc<false><<<ggrid, 256>>>(z, kb, 0.05f, ode_n1w, ode_n1b, g, nullptr);
        ode_conv_mma<0><<<cgrid, 128>>>(g, w1p, t + 0.05f, ode_b1, wc1, u, ka, z);
        gn_nhwc<false><<<ggrid, 256>>>(u, u, 0.f, ode_n2w, ode_n2b, g, nullptr);
        ode_conv_mma<2><<<cgrid, 128>>>(g, w2p, t + 0.05f, ode_b2, wc2, kb, ka, z);
        // k3
        gn_nhwc<false><<<ggrid, 256>>>(z, kb, 0.05f, ode_n1w, ode_n1b, g, nullptr);
        ode_conv_mma<0><<<cgrid, 128>>>(g, w1p, t + 0.05f, ode_b1, wc1, u, ka, z);
        gn_nhwc<false><<<ggrid, 256>>>(u, u, 0.f, ode_n2w, ode_n2b, g, nullptr);
        ode_conv_mma<2><<<cgrid, 128>>>(g, w2p, t + 0.05f, ode_b2, wc2, kb, ka, z);
        // k4
        gn_nhwc<false><<<ggrid, 256>>>(z, kb, 0.1f, ode_n1w, ode_n1b, g, nullptr);
        ode_conv_mma<0><<<cgrid, 128>>>(g, w1p, t + 0.1f, ode_b1, wc1, u, ka, z);
        gn_nhwc<false><<<ggrid, 256>>>(u, u, 0.f, ode_n2w, ode_n2b, g, nullptr);
        ode_conv_mma<3><<<cgrid, 128>>>(g, w2p, t + 0.1f, ode_b2, wc2, kb, ka, z);
    }

    // ---- head ----
    gn_nhwc<true><<<ggrid, 256>>>(z, z, 0.f, head_nw, head_nb, nullptr, pool);
    linear_k<<<(BB * 10 + 255) / 256, 256>>>(pool, head_W, head_b, out);
}